// round 1
// baseline (speedup 1.0000x reference)
#include <cuda_runtime.h>
#include <math.h>

#define B 2
#define S 2048
#define D 512
#define H 8
#define DH 64
#define NB 10

// ---------------- scratch (static device allocations are allowed) ------------
__device__ float g_qp[B*S*D];
__device__ float g_kp[B*S*D];
__device__ float g_vp[B*S*D];
__device__ float g_coef[NB*B*H*S];                 // [n][b][h][s], pre-scaled by 0.1/8
__device__ float g_logits[(size_t)B*H*S*S];        // 268 MB
__device__ float g_attnv[B*S*D];                   // attn @ V, (b,s, h*64+d)

// ---------------- generic tiled GEMM:  C = A(MxK) * W(KxN) + bias ------------
__global__ void gemm_bias_kernel(const float* __restrict__ A, const float* __restrict__ W,
                                 const float* __restrict__ bias, float* __restrict__ C,
                                 int M, int N, int K)
{
    __shared__ float As[16*65];   // [k][m] padded
    __shared__ float Bs[16*64];   // [k][n]
    const int bm = blockIdx.y * 64, bn = blockIdx.x * 64;
    const int tid = threadIdx.x;
    const int tn = tid & 15, tq = tid >> 4;
    const int ar = tid >> 2, ac = (tid & 3) << 2;
    const int br = tid >> 4, bc = (tid & 15) << 2;
    float acc[4][4] = {};
    for (int k0 = 0; k0 < K; k0 += 16) {
        float4 a4 = *(const float4*)&A[(size_t)(bm + ar) * K + k0 + ac];
        As[(ac+0)*65 + ar] = a4.x; As[(ac+1)*65 + ar] = a4.y;
        As[(ac+2)*65 + ar] = a4.z; As[(ac+3)*65 + ar] = a4.w;
        float4 b4 = *(const float4*)&W[(size_t)(k0 + br) * N + bn + bc];
        *(float4*)&Bs[br*64 + bc] = b4;
        __syncthreads();
        #pragma unroll
        for (int k = 0; k < 16; k++) {
            float4 bv = *(const float4*)&Bs[k*64 + tn*4];
            float av[4];
            #pragma unroll
            for (int i = 0; i < 4; i++) av[i] = As[k*65 + tq*4 + i];
            #pragma unroll
            for (int i = 0; i < 4; i++) {
                acc[i][0] += av[i]*bv.x; acc[i][1] += av[i]*bv.y;
                acc[i][2] += av[i]*bv.z; acc[i][3] += av[i]*bv.w;
            }
        }
        __syncthreads();
    }
    float4 bb = *(const float4*)&bias[bn + tn*4];
    #pragma unroll
    for (int i = 0; i < 4; i++) {
        int row = bm + tq*4 + i;
        float4 o = make_float4(acc[i][0] + bb.x, acc[i][1] + bb.y,
                               acc[i][2] + bb.z, acc[i][3] + bb.w);
        *(float4*)&C[(size_t)row * N + bn + tn*4] = o;
    }
}

// ---------------- per-head scalar coefficients -------------------------------
// coef[n,b,h,s] = 0.0125 * f( qp[b,s,:] . Wcoef[n,:,h] + bcoef[n,h] ), f=abs for n==1
__global__ void coef_kernel(const float* __restrict__ Wcoef, const float* __restrict__ bcoef)
{
    const int bs = blockIdx.x;            // 0 .. B*S-1
    const int b = bs / S, s = bs % S;
    __shared__ float sq[D];
    for (int i = threadIdx.x; i < D; i += blockDim.x) sq[i] = g_qp[(size_t)bs * D + i];
    __syncthreads();
    const int t = threadIdx.x;
    if (t < NB * H) {
        const int n = t >> 3, h = t & 7;
        const float* w = Wcoef + (size_t)n * D * H + h;
        float acc = 0.f;
        #pragma unroll 8
        for (int d = 0; d < D; d++) acc += sq[d] * w[(size_t)d * H];
        acc += bcoef[n*H + h];
        if (n == 1) acc = fabsf(acc);
        g_coef[(((size_t)n*B + b)*H + h)*S + s] = 0.0125f * acc;   // 0.1 / sqrt(64)
    }
}

// ---------------- fused basis + coef-dot + QK^T logits ----------------------
// dyn smem: bas[10][64][65] | qs[64][65] | ks[64][65] | cf[10][64]
#define LG_SMEM ((10*64*65 + 64*65 + 64*65 + 10*64) * 4)
__global__ void logits_kernel(const float* __restrict__ xdiff)
{
    extern __shared__ float sm[];
    float* bas = sm;                       // 10 * 4160
    float* qs  = bas + 10*64*65;           // 4160
    float* ks  = qs + 64*65;               // 4160
    float* cf  = ks + 64*65;               // 640

    const int b = blockIdx.z;
    const int q0 = blockIdx.y * 64, k0 = blockIdx.x * 64;
    const int tid = threadIdx.x;

    // basis from xdiff (shared across all heads)
    for (int idx = tid; idx < 64*64; idx += 256) {
        int q = idx >> 6, k = idx & 63;
        float x = xdiff[((size_t)b*S + q0 + q) * S + k0 + k];
        float s1, c1; sincospif(x, &s1, &c1);
        float tc2 = 2.f * (1.f - 2.f*s1*s1);     // 2*cos(2*pi*x)
        float s3 = tc2*s1 + s1,  c3 = tc2*c1 - c1;
        float s5 = tc2*s3 - s1,  c5 = tc2*c3 - c1;
        float s7 = tc2*s5 - s3,  c7 = tc2*c5 - c3;
        float s9 = tc2*s7 - s5,  c9 = tc2*c7 - c5;
        int base = q*65 + k;
        bas[0*4160 + base] = x;
        bas[1*4160 + base] = -0.5f * x * x;
        bas[2*4160 + base] = s1; bas[3*4160 + base] = c1;
        bas[4*4160 + base] = s3; bas[5*4160 + base] = c3;
        bas[6*4160 + base] = s5; bas[7*4160 + base] = c5;
        bas[8*4160 + base] = s9; bas[9*4160 + base] = c9;
    }

    const int tx = tid & 15, ty = tid >> 4;
    const int qb = ty * 4, kb = tx * 4;

    for (int h = 0; h < H; h++) {
        __syncthreads();   // basis ready (h=0) / previous-iter reads done
        for (int idx = tid; idx < 64*16; idx += 256) {
            int q = idx >> 4, c = (idx & 15) * 4;
            float4 v = *(const float4*)&g_qp[((size_t)b*S + q0 + q) * D + h*DH + c];
            qs[q*65+c] = v.x; qs[q*65+c+1] = v.y; qs[q*65+c+2] = v.z; qs[q*65+c+3] = v.w;
        }
        for (int idx = tid; idx < 64*16; idx += 256) {
            int k = idx >> 4, c = (idx & 15) * 4;
            float4 v = *(const float4*)&g_kp[((size_t)b*S + k0 + k) * D + h*DH + c];
            ks[k*65+c] = v.x; ks[k*65+c+1] = v.y; ks[k*65+c+2] = v.z; ks[k*65+c+3] = v.w;
        }
        for (int idx = tid; idx < NB*64; idx += 256) {
            int n = idx >> 6, q = idx & 63;
            cf[idx] = g_coef[(((size_t)n*B + b)*H + h)*S + q0 + q];
        }
        __syncthreads();

        float accb[4][4] = {};
        #pragma unroll
        for (int n = 0; n < NB; n++) {
            float cv[4];
            #pragma unroll
            for (int i = 0; i < 4; i++) cv[i] = cf[n*64 + qb + i];
            #pragma unroll
            for (int i = 0; i < 4; i++)
                #pragma unroll
                for (int j = 0; j < 4; j++)
                    accb[i][j] += cv[i] * bas[n*4160 + (qb+i)*65 + kb + j];
        }
        float accq[4][4] = {};
        #pragma unroll 8
        for (int d = 0; d < DH; d++) {
            float av[4], bv[4];
            #pragma unroll
            for (int i = 0; i < 4; i++) av[i] = qs[(qb+i)*65 + d];
            #pragma unroll
            for (int j = 0; j < 4; j++) bv[j] = ks[(kb+j)*65 + d];
            #pragma unroll
            for (int i = 0; i < 4; i++)
                #pragma unroll
                for (int j = 0; j < 4; j++)
                    accq[i][j] += av[i] * bv[j];
        }
        #pragma unroll
        for (int i = 0; i < 4; i++) {
            size_t rowo = (((size_t)(b*H + h)*S) + q0 + qb + i) * S + k0 + kb;
            float4 o = make_float4(accb[i][0] + 0.125f*accq[i][0],
                                   accb[i][1] + 0.125f*accq[i][1],
                                   accb[i][2] + 0.125f*accq[i][2],
                                   accb[i][3] + 0.125f*accq[i][3]);
            *(float4*)&g_logits[rowo] = o;
        }
    }
}

// ---------------- row softmax: logits -> attn (written to d_out) ------------
__global__ void softmax_kernel(float* __restrict__ attn)
{
    const size_t row = blockIdx.x;                // B*H*S rows
    const float4* in = (const float4*)(g_logits + row * S);
    float4* out = (float4*)(attn + row * S);
    const int t = threadIdx.x;                    // 256
    float4 a = in[t], c = in[256 + t];
    float m = fmaxf(fmaxf(fmaxf(a.x,a.y),fmaxf(a.z,a.w)),
                    fmaxf(fmaxf(c.x,c.y),fmaxf(c.z,c.w)));
    __shared__ float red[8];
    #pragma unroll
    for (int o = 16; o > 0; o >>= 1) m = fmaxf(m, __shfl_xor_sync(0xffffffffu, m, o));
    if ((t & 31) == 0) red[t >> 5] = m;
    __syncthreads();
    m = red[0];
    #pragma unroll
    for (int i = 1; i < 8; i++) m = fmaxf(m, red[i]);

    a.x = expf(a.x - m); a.y = expf(a.y - m); a.z = expf(a.z - m); a.w = expf(a.w - m);
    c.x = expf(c.x - m); c.y = expf(c.y - m); c.z = expf(c.z - m); c.w = expf(c.w - m);
    float s = a.x + a.y + a.z + a.w + c.x + c.y + c.z + c.w;
    #pragma unroll
    for (int o = 16; o > 0; o >>= 1) s += __shfl_xor_sync(0xffffffffu, s, o);
    __syncthreads();           // red reads above complete before overwrite
    if ((t & 31) == 0) red[t >> 5] = s;
    __syncthreads();
    s = red[0];
    #pragma unroll
    for (int i = 1; i < 8; i++) s += red[i];
    float inv = 1.f / s;
    a.x *= inv; a.y *= inv; a.z *= inv; a.w *= inv;
    c.x *= inv; c.y *= inv; c.z *= inv; c.w *= inv;
    out[t] = a; out[256 + t] = c;
}

// ---------------- PV: attnv[b,q, h*64+d] = sum_k attn[b,h,q,k] * vp[b,k,h*64+d]
__global__ void pv_kernel(const float* __restrict__ attn)
{
    __shared__ float at[128*65];
    __shared__ float vs[64*64];
    const int b = blockIdx.z, h = blockIdx.y;
    const int q0 = blockIdx.x * 128;
    const int tid = threadIdx.x;
    const int tx = tid & 15, ty = tid >> 4;
    float acc[8][4] = {};
    const float* arow = attn + ((size_t)(b*H + h)*S + q0) * S;
    for (int k0 = 0; k0 < S; k0 += 64) {
        #pragma unroll
        for (int i = 0; i < 8; i++) {
            int idx = tid + i*256;
            int q = idx >> 4, c = (idx & 15) * 4;
            float4 a4 = *(const float4*)&arow[(size_t)q*S + k0 + c];
            at[q*65+c] = a4.x; at[q*65+c+1] = a4.y; at[q*65+c+2] = a4.z; at[q*65+c+3] = a4.w;
        }
        #pragma unroll
        for (int i = 0; i < 4; i++) {
            int idx = tid + i*256;
            int k = idx >> 4, c = (idx & 15) * 4;
            *(float4*)&vs[k*64 + c] =
                *(const float4*)&g_vp[((size_t)b*S + k0 + k)*D + h*DH + c];
        }
        __syncthreads();
        #pragma unroll 4
        for (int k = 0; k < 64; k++) {
            float4 v4 = *(const float4*)&vs[k*64 + tx*4];
            #pragma unroll
            for (int i = 0; i < 8; i++) {
                float a = at[(ty*8 + i)*65 + k];
                acc[i][0] += a*v4.x; acc[i][1] += a*v4.y;
                acc[i][2] += a*v4.z; acc[i][3] += a*v4.w;
            }
        }
        __syncthreads();
    }
    #pragma unroll
    for (int i = 0; i < 8; i++) {
        int q = q0 + ty*8 + i;
        *(float4*)&g_attnv[((size_t)b*S + q)*D + h*DH + tx*4] =
            make_float4(acc[i][0], acc[i][1], acc[i][2], acc[i][3]);
    }
}

// -----------------------------------------------------------------------------
extern "C" void kernel_launch(void* const* d_in, const int* in_sizes, int n_in,
                              void* d_out, int out_size)
{
    const float* q     = (const float*)d_in[0];
    const float* k     = (const float*)d_in[1];
    const float* v     = (const float*)d_in[2];
    const float* xdiff = (const float*)d_in[3];
    const float* Wq    = (const float*)d_in[4];
    const float* bq    = (const float*)d_in[5];
    const float* Wk    = (const float*)d_in[6];
    const float* bk    = (const float*)d_in[7];
    const float* Wv    = (const float*)d_in[8];
    const float* bv    = (const float*)d_in[9];
    const float* Wcoef = (const float*)d_in[10];
    const float* bcoef = (const float*)d_in[11];
    const float* Wo    = (const float*)d_in[12];
    const float* bo    = (const float*)d_in[13];
    float* out = (float*)d_out;                       // [B*S*D] out | [B*H*S*S] attn
    float* attn = out + (size_t)B*S*D;

    float *qp, *kp, *vp, *av;
    cudaGetSymbolAddress((void**)&qp, g_qp);
    cudaGetSymbolAddress((void**)&kp, g_kp);
    cudaGetSymbolAddress((void**)&vp, g_vp);
    cudaGetSymbolAddress((void**)&av, g_attnv);

    cudaFuncSetAttribute(logits_kernel, cudaFuncAttributeMaxDynamicSharedMemorySize, LG_SMEM);

    dim3 ggrid(D/64, (B*S)/64);
    gemm_bias_kernel<<<ggrid, 256>>>(q, Wq, bq, qp, B*S, D, D);
    gemm_bias_kernel<<<ggrid, 256>>>(k, Wk, bk, kp, B*S, D, D);
    gemm_bias_kernel<<<ggrid, 256>>>(v, Wv, bv, vp, B*S, D, D);

    coef_kernel<<<B*S, 128>>>(Wcoef, bcoef);

    logits_kernel<<<dim3(S/64, S/64, B), 256, LG_SMEM>>>(xdiff);

    softmax_kernel<<<B*H*S, 256>>>(attn);

    pv_kernel<<<dim3(S/128, H, B), 256>>>(attn);

    gemm_bias_kernel<<<ggrid, 256>>>(av, Wo, bo, out, B*S, D, D);
}